// round 3
// baseline (speedup 1.0000x reference)
#include <cuda_runtime.h>
#include <mma.h>
#include <math.h>
#include <stdint.h>

using namespace nvcuda;

// Problem constants
#define T_LEN   4096
#define B_SZ    32
#define D_MODEL 256
#define H_DIM   512
#define KFREQ   128
#define LN_EPS  1e-5f

// ---------------- device scratch (no allocations allowed) ----------------
__device__ float g_lutc[T_LEN];
__device__ float g_luts[T_LEN];
__device__ float g_ren[B_SZ * KFREQ];    // cos(phase0)
__device__ float g_imn[B_SZ * KFREQ];    // sin(phase0)
__device__ float g_base[B_SZ * H_DIM];   // mag @ w1[:128,:] + b1

// ---------------- kernel 0: twiddle LUT (for spectral kernel only) ----------------
__global__ void lut_kernel() {
    int i = blockIdx.x * blockDim.x + threadIdx.x;
    if (i < T_LEN) {
        float ph = (float)((double)i * 1.5339807878856412e-3);
        float s, c;
        sincosf(ph, &s, &c);
        g_lutc[i] = c;
        g_luts[i] = s;
    }
}

// ---------------- kernel 1: DFT bins + normalized phase + base ----------------
#define SPEC_SMEM_FLOATS (T_LEN * 3 + KFREQ)
__global__ __launch_bounds__(256) void spectral_kernel(
    const int* __restrict__ byte_ids,
    const float* __restrict__ freq_bands,
    const float* __restrict__ w1,
    const float* __restrict__ b1)
{
    extern __shared__ float sm[];
    float* sig  = sm;
    float* lc   = sm + T_LEN;
    float* ls   = sm + 2 * T_LEN;
    float* magS = sm + 3 * T_LEN;

    int b   = blockIdx.x;
    int tid = threadIdx.x;

    for (int i = tid; i < T_LEN; i += 256) {
        sig[i] = (float)byte_ids[b * T_LEN + i] * (1.0f / 127.5f) - 1.0f;
        lc[i]  = g_lutc[i];
        ls[i]  = g_luts[i];
    }
    __syncthreads();

    int warp = tid >> 5, lane = tid & 31;
    for (int f = warp; f < KFREQ; f += 8) {
        float cacc = 0.f, sacc = 0.f;
        int idx  = (lane * f) & (T_LEN - 1);
        int step = (32 * f) & (T_LEN - 1);
        for (int i = lane; i < T_LEN; i += 32) {
            float sv = sig[i];
            cacc += sv * lc[idx];
            sacc += sv * ls[idx];
            idx = (idx + step) & (T_LEN - 1);
        }
        #pragma unroll
        for (int o = 16; o; o >>= 1) {
            cacc += __shfl_xor_sync(0xffffffffu, cacc, o);
            sacc += __shfl_xor_sync(0xffffffffu, sacc, o);
        }
        if (lane == 0) {
            float re = cacc, im = -sacc;
            float hyp = sqrtf(re * re + im * im);
            float rn, in_;
            if (hyp > 1e-30f) {
                float inv = 1.0f / hyp;
                rn = re * inv; in_ = im * inv;
            } else {
                rn = 1.0f; in_ = 0.0f;
            }
            g_ren[b * KFREQ + f] = rn;
            g_imn[b * KFREQ + f] = in_;
            magS[f] = hyp * freq_bands[f];
        }
    }
    __syncthreads();

    for (int j = tid; j < H_DIM; j += 256) {
        float acc = b1[j];
        for (int f = 0; f < KFREQ; f++)
            acc += magS[f] * w1[f * H_DIM + j];
        g_base[b * H_DIM + j] = acc;
    }
}

// ---------------- kernel 2: fused  A@W1b -> +base -> LN -> GELU -> @W2 -> +b2 ----------------
// A[t,f] = imn[f]*cos(2pi t f/T) + ren[f]*sin(2pi t f/T), sincos computed on the fly.
// grid = 2048 (32 batches * 64 tiles of 64 rows), block = 512 threads (16 warps)
// Double-buffered B/A staging, ONE __syncthreads per K-chunk.
// smem (floats):
//   hsm  [64*520]              h / g / C2 staging (ld=520)
//   Bd   [2 * 8320]            GEMM1 chunk 16x516 (8256) / GEMM2 chunk 32x260 (8320), double buffered
//   A1d  [2 * 64*20]           GEMM1 A chunks (ld=20)
//   imnS[128], renS[128]
#define HSM_LD   520
#define B1_LD    516
#define B2_LD    260
#define A1_LD    20
#define B_BUF    8320
#define A_BUF    (64 * A1_LD)
#define OFF_HSM  0
#define OFF_B    (64 * HSM_LD)
#define OFF_A    (OFF_B + 2 * B_BUF)
#define OFF_IMN  (OFF_A + 2 * A_BUF)
#define OFF_REN  (OFF_IMN + KFREQ)
#define FUSED_SMEM_FLOATS (OFF_REN + KFREQ)
#define PHSTEP   1.5339807878856412e-3f   // 2*pi/4096

__global__ __launch_bounds__(512, 1) void fused_kernel(
    const float* __restrict__ w1,
    const float* __restrict__ w2,
    const float* __restrict__ gamma,
    const float* __restrict__ beta,
    const float* __restrict__ b2v,
    float* __restrict__ out)
{
    extern __shared__ float sm[];
    float* hsm  = sm + OFF_HSM;
    float* Bd   = sm + OFF_B;
    float* A1d  = sm + OFF_A;
    float* imnS = sm + OFF_IMN;
    float* renS = sm + OFF_REN;

    int tid = threadIdx.x;
    int blk = blockIdx.x;
    int b   = blk >> 6;
    int t0  = (blk & 63) * 64;

    if (tid < KFREQ) {
        imnS[tid] = g_imn[b * KFREQ + tid];
        renS[tid] = g_ren[b * KFREQ + tid];
    }
    __syncthreads();

    int warp = tid >> 5, lane = tid & 31;
    int wm = warp >> 3, wn = warp & 7;

    // ================= GEMM1: C1(64x512) = A(64x128) @ W1b(128x512) =================
    // K-chunks of 16, 8 iterations, double buffered.
    wmma::fragment<wmma::accumulator, 16, 16, 8, float> c1[2][4];
    #pragma unroll
    for (int im = 0; im < 2; im++)
        #pragma unroll
        for (int jn = 0; jn < 4; jn++)
            wmma::fill_fragment(c1[im][jn], 0.0f);

    // A generation: 64x16 chunk = 1024 elems, 2 per thread
    int ae0 = tid, ae1 = tid + 512;
    int ar0 = ae0 >> 4, ac0 = ae0 & 15;
    int ar1 = ae1 >> 4, ac1 = ae1 & 15;

    float breg[16];
    float av0, av1;

    // prefetch chunk 0
    {
        #pragma unroll
        for (int i = 0; i < 16; i++) breg[i] = w1[(KFREQ + i) * H_DIM + tid];
        int f0c = ac0, t0c = t0 + ar0;
        int idx = (t0c * f0c) & (T_LEN - 1); if (idx >= T_LEN / 2) idx -= T_LEN;
        float s0, c0; __sincosf((float)idx * PHSTEP, &s0, &c0);
        av0 = imnS[f0c] * c0 + renS[f0c] * s0;
        int f1c = ac1, t1c = t0 + ar1;
        idx = (t1c * f1c) & (T_LEN - 1); if (idx >= T_LEN / 2) idx -= T_LEN;
        float s1, c1v; __sincosf((float)idx * PHSTEP, &s1, &c1v);
        av1 = imnS[f1c] * c1v + renS[f1c] * s1;
    }
    // stage chunk 0 into buffer 0
    {
        float* B1s = Bd;
        float* A1s = A1d;
        #pragma unroll
        for (int i = 0; i < 16; i++) B1s[i * B1_LD + tid] = wmma::__float_to_tf32(breg[i]);
        A1s[ar0 * A1_LD + ac0] = wmma::__float_to_tf32(av0);
        A1s[ar1 * A1_LD + ac1] = wmma::__float_to_tf32(av1);
    }
    __syncthreads();

    for (int kc = 0; kc < 8; kc++) {
        int cur = kc & 1;
        float* B1s = Bd  + cur * B_BUF;
        float* A1s = A1d + cur * A_BUF;

        // prefetch next chunk into registers (hidden under MMA)
        if (kc < 7) {
            int f0 = (kc + 1) * 16;
            #pragma unroll
            for (int i = 0; i < 16; i++) breg[i] = w1[(KFREQ + f0 + i) * H_DIM + tid];
            int fc = f0 + ac0, tc = t0 + ar0;
            int idx = (tc * fc) & (T_LEN - 1); if (idx >= T_LEN / 2) idx -= T_LEN;
            float s0, c0; __sincosf((float)idx * PHSTEP, &s0, &c0);
            av0 = imnS[fc] * c0 + renS[fc] * s0;
            fc = f0 + ac1; tc = t0 + ar1;
            idx = (tc * fc) & (T_LEN - 1); if (idx >= T_LEN / 2) idx -= T_LEN;
            float s1, c1v; __sincosf((float)idx * PHSTEP, &s1, &c1v);
            av1 = imnS[fc] * c1v + renS[fc] * s1;
        }

        // MMA on current buffer: 2 k-steps of 8
        #pragma unroll
        for (int ks = 0; ks < 2; ks++) {
            wmma::fragment<wmma::matrix_a, 16, 16, 8, wmma::precision::tf32, wmma::row_major> afr[2];
            #pragma unroll
            for (int im = 0; im < 2; im++)
                wmma::load_matrix_sync(afr[im], A1s + (32 * wm + 16 * im) * A1_LD + 8 * ks, A1_LD);
            #pragma unroll
            for (int jn = 0; jn < 4; jn++) {
                wmma::fragment<wmma::matrix_b, 16, 16, 8, wmma::precision::tf32, wmma::row_major> bfr;
                wmma::load_matrix_sync(bfr, B1s + (8 * ks) * B1_LD + 64 * wn + 16 * jn, B1_LD);
                #pragma unroll
                for (int im = 0; im < 2; im++)
                    wmma::mma_sync(c1[im][jn], afr[im], bfr, c1[im][jn]);
            }
        }

        // stage prefetched chunk into the other buffer
        if (kc < 7) {
            float* B1n = Bd  + (cur ^ 1) * B_BUF;
            float* A1n = A1d + (cur ^ 1) * A_BUF;
            #pragma unroll
            for (int i = 0; i < 16; i++) B1n[i * B1_LD + tid] = wmma::__float_to_tf32(breg[i]);
            A1n[ar0 * A1_LD + ac0] = wmma::__float_to_tf32(av0);
            A1n[ar1 * A1_LD + ac1] = wmma::__float_to_tf32(av1);
        }
        __syncthreads();
    }

    // store C1 tiles into hsm
    #pragma unroll
    for (int im = 0; im < 2; im++)
        #pragma unroll
        for (int jn = 0; jn < 4; jn++)
            wmma::store_matrix_sync(hsm + (32 * wm + 16 * im) * HSM_LD + 64 * wn + 16 * jn,
                                    c1[im][jn], HSM_LD, wmma::mem_row_major);
    __syncthreads();

    // ================= LayerNorm + exact GELU =================
    {
        const float* baseP = g_base + b * H_DIM;
        for (int rr = 0; rr < 4; rr++) {
            int r = warp * 4 + rr;
            float x[16];
            float s1 = 0.f, s2 = 0.f;
            #pragma unroll
            for (int q = 0; q < 16; q++) {
                int j = q * 32 + lane;
                float v = hsm[r * HSM_LD + j] + baseP[j];
                x[q] = v; s1 += v; s2 += v * v;
            }
            #pragma unroll
            for (int o = 16; o; o >>= 1) {
                s1 += __shfl_xor_sync(0xffffffffu, s1, o);
                s2 += __shfl_xor_sync(0xffffffffu, s2, o);
            }
            float mean = s1 * (1.0f / H_DIM);
            float var  = s2 * (1.0f / H_DIM) - mean * mean;
            float rstd = rsqrtf(var + LN_EPS);
            #pragma unroll
            for (int q = 0; q < 16; q++) {
                int j = q * 32 + lane;
                float y = (x[q] - mean) * rstd * gamma[j] + beta[j];
                float g = 0.5f * y * (1.0f + erff(y * 0.70710678118654752f));
                hsm[r * HSM_LD + j] = wmma::__float_to_tf32(g);
            }
        }
    }
    __syncthreads();

    // ================= GEMM2: C2(64x256) = g(64x512) @ W2(512x256) =================
    // K-chunks of 32, 16 iterations, double buffered.
    wmma::fragment<wmma::accumulator, 16, 16, 8, float> c2[2][2];
    #pragma unroll
    for (int im = 0; im < 2; im++)
        #pragma unroll
        for (int jn = 0; jn < 2; jn++)
            wmma::fill_fragment(c2[im][jn], 0.0f);

    int j2 = tid & 255, r0 = tid >> 8;   // rows r0 + 2*i (i=0..15), column j2
    float breg2[16];
    // prefetch chunk 0
    #pragma unroll
    for (int i = 0; i < 16; i++) breg2[i] = w2[(r0 + 2 * i) * D_MODEL + j2];
    // stage chunk 0 into buffer 0
    {
        float* B2s = Bd;
        #pragma unroll
        for (int i = 0; i < 16; i++)
            B2s[(r0 + 2 * i) * B2_LD + j2] = wmma::__float_to_tf32(breg2[i]);
    }
    __syncthreads();

    for (int kc = 0; kc < 16; kc++) {
        int cur = kc & 1;
        float* B2s = Bd + cur * B_BUF;

        if (kc < 15) {
            int kb = (kc + 1) * 32;
            #pragma unroll
            for (int i = 0; i < 16; i++)
                breg2[i] = w2[(kb + r0 + 2 * i) * D_MODEL + j2];
        }

        // MMA: 4 k-steps of 8
        #pragma unroll
        for (int ks = 0; ks < 4; ks++) {
            wmma::fragment<wmma::matrix_a, 16, 16, 8, wmma::precision::tf32, wmma::row_major> a2[2];
            #pragma unroll
            for (int im = 0; im < 2; im++)
                wmma::load_matrix_sync(a2[im], hsm + (32 * wm + 16 * im) * HSM_LD + kc * 32 + 8 * ks, HSM_LD);
            #pragma unroll
            for (int jn = 0; jn < 2; jn++) {
                wmma::fragment<wmma::matrix_b, 16, 16, 8, wmma::precision::tf32, wmma::row_major> b2fr;
                wmma::load_matrix_sync(b2fr, B2s + (8 * ks) * B2_LD + 32 * wn + 16 * jn, B2_LD);
                #pragma unroll
                for (int im = 0; im < 2; im++)
                    wmma::mma_sync(c2[im][jn], a2[im], b2fr, c2[im][jn]);
            }
        }

        if (kc < 15) {
            float* B2n = Bd + (cur ^ 1) * B_BUF;
            #pragma unroll
            for (int i = 0; i < 16; i++)
                B2n[(r0 + 2 * i) * B2_LD + j2] = wmma::__float_to_tf32(breg2[i]);
        }
        __syncthreads();
    }

    // stage C2 into hsm (cols 0..255), then epilogue +b2 -> gmem (float4)
    #pragma unroll
    for (int im = 0; im < 2; im++)
        #pragma unroll
        for (int jn = 0; jn < 2; jn++)
            wmma::store_matrix_sync(hsm + (32 * wm + 16 * im) * HSM_LD + 32 * wn + 16 * jn,
                                    c2[im][jn], HSM_LD, wmma::mem_row_major);
    __syncthreads();

    const float4* b2v4 = (const float4*)b2v;
    float4* out4 = (float4*)(out + (size_t)(b * T_LEN + t0) * D_MODEL);
    #pragma unroll
    for (int q = 0; q < 8; q++) {
        int e  = q * 512 + tid;        // 0..4095 float4 slots
        int r  = e >> 6;               // row 0..63
        int j4 = e & 63;               // float4 col
        float4 v = *(const float4*)(hsm + r * HSM_LD + 4 * j4);
        float4 bb = b2v4[j4];
        v.x += bb.x; v.y += bb.y; v.z += bb.z; v.w += bb.w;
        out4[(size_t)r * (D_MODEL / 4) + j4] = v;
    }
}

// ---------------- launch ----------------
extern "C" void kernel_launch(void* const* d_in, const int* in_sizes, int n_in,
                              void* d_out, int out_size) {
    const int*   byte_ids = (const int*)  d_in[0];
    const float* fb       = (const float*)d_in[1];
    const float* w1       = (const float*)d_in[2];
    const float* b1       = (const float*)d_in[3];
    const float* gamma    = (const float*)d_in[4];
    const float* beta     = (const float*)d_in[5];
    const float* w2       = (const float*)d_in[6];
    const float* b2v      = (const float*)d_in[7];
    float* out = (float*)d_out;

    (void)in_sizes; (void)n_in; (void)out_size;

    cudaFuncSetAttribute(spectral_kernel, cudaFuncAttributeMaxDynamicSharedMemorySize,
                         SPEC_SMEM_FLOATS * (int)sizeof(float));
    cudaFuncSetAttribute(fused_kernel, cudaFuncAttributeMaxDynamicSharedMemorySize,
                         FUSED_SMEM_FLOATS * (int)sizeof(float));

    lut_kernel<<<(T_LEN + 255) / 256, 256>>>();
    spectral_kernel<<<B_SZ, 256, SPEC_SMEM_FLOATS * sizeof(float)>>>(byte_ids, fb, w1, b1);
    fused_kernel<<<B_SZ * (T_LEN / 64), 512, FUSED_SMEM_FLOATS * sizeof(float)>>>(
        w1, w2, gamma, beta, b2v, out);
}

// round 8
// speedup vs baseline: 1.8442x; 1.8442x over previous
#include <cuda_runtime.h>
#include <cuda_fp16.h>
#include <math.h>
#include <stdint.h>

// Problem constants
#define T_LEN   4096
#define B_SZ    32
#define D_MODEL 256
#define H_DIM   512
#define KFREQ   128
#define LN_EPS  1e-5f
#define PHSTEP  1.5339807878856412e-3f   // 2*pi/4096
#define NROWS   (B_SZ * T_LEN)           // 131072

// ---------------- device scratch (static; no allocations) ----------------
__device__ float g_ren[B_SZ * KFREQ];
__device__ float g_imn[B_SZ * KFREQ];
__device__ float g_base[B_SZ * H_DIM];
__device__ __align__(16) __half g_w1h[4 * 512 * 40];     // w1b fp16, 4 k32-chunks, [n][k] LDk=40
__device__ __align__(16) __half g_w2h[8 * 256 * 72];     // w2  fp16, 8 k64-chunks, [n][k] LDk=72
__device__ __align__(16) __half g_h[(size_t)NROWS * H_DIM]; // 128MB intermediate (post-GELU fp16)

// ---------------- helpers ----------------
__device__ __forceinline__ uint32_t smem_u32(const void* p) {
    uint32_t a;
    asm("{ .reg .u64 t; cvta.to.shared.u64 t, %1; cvt.u32.u64 %0, t; }" : "=r"(a) : "l"(p));
    return a;
}
__device__ __forceinline__ void cp16(uint32_t dst, const void* src) {
    asm volatile("cp.async.cg.shared.global [%0], [%1], 16;" :: "r"(dst), "l"(src) : "memory");
}
__device__ __forceinline__ void cp_commit() { asm volatile("cp.async.commit_group;" ::: "memory"); }
__device__ __forceinline__ void cp_wait1()  { asm volatile("cp.async.wait_group 1;" ::: "memory"); }
__device__ __forceinline__ void cp_wait0()  { asm volatile("cp.async.wait_group 0;" ::: "memory"); }

// m16n8k16 row.col f32.f16.f16.f32 — documented layouts:
// A: a0=(g,2t|2t+1) a1=(g+8,·) a2=(g,2t+8|9) a3=(g+8,·)   [g=lane>>2, t=lane&3]
// B: b0=(k=2t|2t+1, n=g) b1=(k=2t+8|9, n=g)
// D: d0=(g,2t) d1=(g,2t+1) d2=(g+8,2t) d3=(g+8,2t+1)
__device__ __forceinline__ void mma_f16(float* d, const uint32_t* a, uint32_t b0, uint32_t b1) {
    asm volatile(
        "mma.sync.aligned.m16n8k16.row.col.f32.f16.f16.f32 "
        "{%0,%1,%2,%3}, {%4,%5,%6,%7}, {%8,%9}, {%0,%1,%2,%3};"
        : "+f"(d[0]), "+f"(d[1]), "+f"(d[2]), "+f"(d[3])
        : "r"(a[0]), "r"(a[1]), "r"(a[2]), "r"(a[3]), "r"(b0), "r"(b1));
}

// ---------------- kernel: weight prep (fp16 images, padded conflict-free layouts) ----------------
__global__ __launch_bounds__(256) void prep_kernel(const float* __restrict__ w1,
                                                   const float* __restrict__ w2) {
    int i = blockIdx.x * 256 + threadIdx.x;
    if (i < 512 * 128) {                       // w1b: n=0..511, k=0..127
        int n = i >> 7, k = i & 127;
        g_w1h[((k >> 5) * 512 + n) * 40 + (k & 31)] = __float2half_rn(w1[(KFREQ + k) * H_DIM + n]);
    } else {
        int j = i - 512 * 128;                 // w2: n=0..255, k=0..511
        if (j < 256 * 512) {
            int n = j >> 9, k = j & 511;
            g_w2h[((k >> 6) * 256 + n) * 72 + (k & 63)] = __float2half_rn(w2[k * D_MODEL + n]);
        }
    }
}

// ---------------- kernel: spectral (DFT bins, normalized phase, base) ----------------
#define SPEC_SMEM_FLOATS (T_LEN * 3 + KFREQ)
__global__ __launch_bounds__(256) void spectral_kernel(
    const int* __restrict__ byte_ids,
    const float* __restrict__ freq_bands,
    const float* __restrict__ w1,
    const float* __restrict__ b1)
{
    extern __shared__ float sm[];
    float* sig  = sm;
    float* lc   = sm + T_LEN;
    float* ls   = sm + 2 * T_LEN;
    float* magS = sm + 3 * T_LEN;

    int b   = blockIdx.x;
    int tid = threadIdx.x;

    for (int i = tid; i < T_LEN; i += 256) {
        sig[i] = (float)byte_ids[b * T_LEN + i] * (1.0f / 127.5f) - 1.0f;
        float s, c;
        sincosf((float)i * PHSTEP, &s, &c);
        lc[i] = c; ls[i] = s;
    }
    __syncthreads();

    int warp = tid >> 5, lane = tid & 31;
    for (int f = warp; f < KFREQ; f += 8) {
        float cacc = 0.f, sacc = 0.f;
        int idx  = (lane * f) & (T_LEN - 1);
        int step = (32 * f) & (T_LEN - 1);
        for (int i = lane; i < T_LEN; i += 32) {
            float sv = sig[i];
            cacc += sv * lc[idx];
            sacc += sv * ls[idx];
            idx = (idx + step) & (T_LEN - 1);
        }
        #pragma unroll
        for (int o = 16; o; o >>= 1) {
            cacc += __shfl_xor_sync(0xffffffffu, cacc, o);
            sacc += __shfl_xor_sync(0xffffffffu, sacc, o);
        }
        if (lane == 0) {
            float re = cacc, im = -sacc;
            float hyp = sqrtf(re * re + im * im);
            float rn = 1.0f, in_ = 0.0f;
            if (hyp > 1e-30f) { float inv = 1.0f / hyp; rn = re * inv; in_ = im * inv; }
            g_ren[b * KFREQ + f] = rn;
            g_imn[b * KFREQ + f] = in_;
            magS[f] = hyp * freq_bands[f];
        }
    }
    __syncthreads();

    for (int j = tid; j < H_DIM; j += 256) {
        float acc = b1[j];
        for (int f = 0; f < KFREQ; f++)
            acc += magS[f] * w1[f * H_DIM + j];
        g_base[b * H_DIM + j] = acc;
    }
}

// ---------------- kernel: GEMM1 + LN + GELU -> g_h (fp16) ----------------
// C(64x512) = A(64x128) @ W1b(128x512); grid = 2048 (32 b x 64 tiles), 512 threads (16 warps: 2m x 8n)
// Warp tile 32m x 64n. A smem [64][136] halfwords. B chunks [512][40] halfwords, double-buffered.
#define G1_OFF_A    0
#define G1_OFF_B    17408
#define G1_OFF_LN1  99328
#define G1_OFF_LN2  101376
#define G1_OFF_BASE 103424
#define G1_OFF_GAM  105472
#define G1_OFF_BET  107520
#define G1_OFF_IMN  109568
#define G1_OFF_REN  110080
#define G1_SMEM_BYTES 110592

__global__ __launch_bounds__(512, 1) void gemm1_kernel(
    const float* __restrict__ gamma,
    const float* __restrict__ beta)
{
    extern __shared__ char smc[];
    __half* As   = (__half*)(smc + G1_OFF_A);
    float*  ln1  = (float*)(smc + G1_OFF_LN1);
    float*  ln2  = (float*)(smc + G1_OFF_LN2);
    float*  baseS= (float*)(smc + G1_OFF_BASE);
    float*  gamS = (float*)(smc + G1_OFF_GAM);
    float*  betS = (float*)(smc + G1_OFF_BET);
    float*  imnS = (float*)(smc + G1_OFF_IMN);
    float*  renS = (float*)(smc + G1_OFF_REN);

    int tid  = threadIdx.x;
    int warp = tid >> 5, lane = tid & 31;
    int g    = lane >> 2, tg = lane & 3;
    int wm   = warp >> 3, wn = warp & 7;      // 2 x 8
    int b    = blockIdx.x >> 6;
    int t0   = (blockIdx.x & 63) * 64;

    if (tid < 128) { imnS[tid] = g_imn[b * KFREQ + tid]; renS[tid] = g_ren[b * KFREQ + tid]; }
    baseS[tid] = g_base[b * H_DIM + tid];
    gamS[tid]  = gamma[tid];
    betS[tid]  = beta[tid];
    __syncthreads();

    // generate A (64 x 128) fp16 into smem, LDk=136 halfwords
    for (int e = tid; e < 64 * 128; e += 512) {
        int m = e >> 7, k = e & 127;
        int idx = ((t0 + m) * k) & (T_LEN - 1);
        if (idx >= T_LEN / 2) idx -= T_LEN;
        float s, c;
        __sincosf((float)idx * PHSTEP, &s, &c);
        As[m * 136 + k] = __float2half_rn(imnS[k] * c + renS[k] * s);
    }

    uint32_t bbuf[2] = { smem_u32(smc + G1_OFF_B), smem_u32(smc + G1_OFF_B + 40960) };
    // prefetch B chunk 0 (linear: image layout == smem layout), 2560 x 16B
    {
        const char* src = (const char*)g_w1h;
        #pragma unroll
        for (int i = 0; i < 5; i++) { int e = tid + i * 512; cp16(bbuf[0] + e * 16, src + e * 16); }
        cp_commit();
    }

    float acc[2][8][4];
    #pragma unroll
    for (int mt = 0; mt < 2; mt++)
        #pragma unroll
        for (int nt = 0; nt < 8; nt++)
            #pragma unroll
            for (int d = 0; d < 4; d++) acc[mt][nt][d] = 0.f;

    const uint32_t* ap = (const uint32_t*)As;

    for (int c = 0; c < 4; c++) {
        if (c < 3) {
            const char* src = (const char*)g_w1h + (c + 1) * 40960;
            uint32_t dst = bbuf[(c + 1) & 1];
            #pragma unroll
            for (int i = 0; i < 5; i++) { int e = tid + i * 512; cp16(dst + e * 16, src + e * 16); }
            cp_commit();
            cp_wait1();
        } else {
            cp_wait0();
        }
        __syncthreads();

        const uint32_t* bp = (const uint32_t*)(smc + G1_OFF_B + (c & 1) * 40960);
        #pragma unroll
        for (int ks = 0; ks < 2; ks++) {
            uint32_t a[2][4];
            #pragma unroll
            for (int mt = 0; mt < 2; mt++) {
                int m = 32 * wm + 16 * mt + g;
                int w0 = m * 68 + c * 16 + ks * 8 + tg;
                a[mt][0] = ap[w0];
                a[mt][1] = ap[w0 + 8 * 68];
                a[mt][2] = ap[w0 + 4];
                a[mt][3] = ap[w0 + 8 * 68 + 4];
            }
            #pragma unroll
            for (int nt = 0; nt < 8; nt++) {
                int n = wn * 64 + nt * 8 + g;
                int w = n * 20 + ks * 8 + tg;
                uint32_t b0 = bp[w], b1 = bp[w + 4];
                mma_f16(acc[0][nt], a[0], b0, b1);
                mma_f16(acc[1][nt], a[1], b0, b1);
            }
        }
        __syncthreads();
    }

    // ---- +base, LN stats ----
    #pragma unroll
    for (int mt = 0; mt < 2; mt++)
        #pragma unroll
        for (int nt = 0; nt < 8; nt++) {
            int j0 = wn * 64 + nt * 8 + 2 * tg;
            acc[mt][nt][0] += baseS[j0];
            acc[mt][nt][1] += baseS[j0 + 1];
            acc[mt][nt][2] += baseS[j0];
            acc[mt][nt][3] += baseS[j0 + 1];
        }

    #pragma unroll
    for (int mt = 0; mt < 2; mt++)
        #pragma unroll
        for (int h = 0; h < 2; h++) {
            float s1 = 0.f, s2 = 0.f;
            #pragma unroll
            for (int nt = 0; nt < 8; nt++) {
                float v0 = acc[mt][nt][2 * h], v1 = acc[mt][nt][2 * h + 1];
                s1 += v0 + v1; s2 += v0 * v0 + v1 * v1;
            }
            s1 += __shfl_xor_sync(0xffffffffu, s1, 1); s2 += __shfl_xor_sync(0xffffffffu, s2, 1);
            s1 += __shfl_xor_sync(0xffffffffu, s1, 2); s2 += __shfl_xor_sync(0xffffffffu, s2, 2);
            if (tg == 0) {
                int r = 32 * wm + 16 * mt + g + 8 * h;
                ln1[r * 8 + wn] = s1;
                ln2[r * 8 + wn] = s2;
            }
        }
    __syncthreads();

    float mean[2][2], rstd[2][2];
    #pragma unroll
    for (int mt = 0; mt < 2; mt++)
        #pragma unroll
        for (int h = 0; h < 2; h++) {
            int r = 32 * wm + 16 * mt + g + 8 * h;
            float t1 = 0.f, t2 = 0.f;
            #pragma unroll
            for (int w = 0; w < 8; w++) { t1 += ln1[r * 8 + w]; t2 += ln2[r * 8 + w]; }
            float mu = t1 * (1.0f / H_DIM);
            float va = t2 * (1.0f / H_DIM) - mu * mu;
            mean[mt][h] = mu;
            rstd[mt][h] = rsqrtf(va + LN_EPS);
        }

    // ---- GELU + store fp16 to g_h ----
    #pragma unroll
    for (int mt = 0; mt < 2; mt++) {
        size_t rg0 = (size_t)(b * T_LEN + t0 + 32 * wm + 16 * mt + g);
        size_t rg1 = rg0 + 8;
        #pragma unroll
        for (int nt = 0; nt < 8; nt++) {
            int j0 = wn * 64 + nt * 8 + 2 * tg;
            float ga = gamS[j0], gb = gamS[j0 + 1], ba = betS[j0], bb = betS[j0 + 1];
            float y00 = (acc[mt][nt][0] - mean[mt][0]) * rstd[mt][0] * ga + ba;
            float y01 = (acc[mt][nt][1] - mean[mt][0]) * rstd[mt][0] * gb + bb;
            float y10 = (acc[mt][nt][2] - mean[mt][1]) * rstd[mt][1] * ga + ba;
            float y11 = (acc[mt][nt][3] - mean[mt][1]) * rstd[mt][1] * gb + bb;
            float g00 = 0.5f * y00 * (1.0f + erff(y00 * 0.70710678118654752f));
            float g01 = 0.5f * y01 * (1.0f + erff(y01 * 0.70710678118654752f));
            float g10 = 0.5f * y10 * (1.0f + erff(y10 * 0.70710678118654752f));
            float g11 = 0.5f * y11 * (1.0f + erff(y11 * 0.70710678118654752f));
            *(__half2*)&g_h[rg0 * H_DIM + j0] = __floats2half2_rn(g00, g01);
            *(__half2*)&g_h[rg1 * H_DIM + j0] = __floats2half2_rn(g10, g11);
        }
    }
}

// ---------------- kernel: GEMM2 + bias -> out ----------------
// C(128x256) = h(128x512) @ W2(512x256); grid = 1024, 512 threads (16 warps: 4m x 4n)
// Warp tile 32m x 64n. k64 chunks: A [128][72]hw, B [256][72]hw, both double-buffered.
#define G2_OFF_A   0
#define G2_OFF_B   36864
#define G2_OFF_B2  110592
#define G2_SMEM_BYTES 111616

__global__ __launch_bounds__(512, 1) void gemm2_kernel(
    const float* __restrict__ b2v,
    float* __restrict__ out)
{
    extern __shared__ char smc[];
    float* b2S = (float*)(smc + G2_OFF_B2);

    int tid  = threadIdx.x;
    int warp = tid >> 5, lane = tid & 31;
    int g    = lane >> 2, tg = lane & 3;
    int wm   = warp & 3, wn = warp >> 2;      // 4 x 4
    size_t r0g = (size_t)blockIdx.x * 128;

    if (tid < 256) b2S[tid] = b2v[tid];

    uint32_t abuf[2] = { smem_u32(smc + G2_OFF_A), smem_u32(smc + G2_OFF_A + 18432) };
    uint32_t bbuf[2] = { smem_u32(smc + G2_OFF_B), smem_u32(smc + G2_OFF_B + 36864) };

    // prefetch chunk 0
    {
        const char* hb = (const char*)g_h;
        #pragma unroll
        for (int i = 0; i < 2; i++) {
            int e = tid + i * 512;            // 1024 x 16B for A
            int m = e >> 3, q = e & 7;
            cp16(abuf[0] + m * 144 + q * 16, hb + ((r0g + m) * 1024) + q * 16);
        }
        const char* wb = (const char*)g_w2h;
        for (int e = tid; e < 2304; e += 512) cp16(bbuf[0] + e * 16, wb + e * 16);
        cp_commit();
    }

    float acc[2][8][4];
    #pragma unroll
    for (int mt = 0; mt < 2; mt++)
        #pragma unroll
        for (int nt = 0; nt < 8; nt++)
            #pragma unroll
            for (int d = 0; d < 4; d++) acc[mt][nt][d] = 0.f;

    for (int c = 0; c < 8; c++) {
        if (c < 7) {
            int nb = (c + 1) & 1;
            const char* hb = (const char*)g_h;
            #pragma unroll
            for (int i = 0; i < 2; i++) {
                int e = tid + i * 512;
                int m = e >> 3, q = e & 7;
                cp16(abuf[nb] + m * 144 + q * 16, hb + ((r0g + m) * 1024) + (size_t)(c + 1) * 128 + q * 16);
            }
            const char* wb = (const char*)g_w2h + (size_t)(c + 1) * 36864;
            for (int e = tid; e < 2304; e += 512) cp16(bbuf[nb] + e * 16, wb + e * 16);
            cp_commit();
            cp_wait1();
        } else {
            cp_wait0();
        }
        __syncthreads();

        const uint32_t* ap = (const uint32_t*)(smc + G2_OFF_A + (c & 1) * 18432);
        const uint32_t* bp = (const uint32_t*)(smc + G2_OFF_B + (c & 1) * 36864);
        #pragma unroll
        for (int ks = 0; ks < 4; ks++) {
            uint32_t a[2][4];
            #pragma unroll
            for (int mt = 0; mt < 2; mt++) {
                int m = 32 * wm + 16 * mt + g;
                int w0 = m * 36 + ks * 8 + tg;
                a[mt][0] = ap[w0];
                a[mt][1] = ap[w0 + 8 * 36];
                a[mt][2] = ap[w0 + 4];
                a[mt][3] = ap[w0 + 8 * 36 + 4];
            }
            #pragma unroll
            for (int nt = 0; nt < 8; nt++) {
                int n = wn * 64 + nt * 8 + g;
                int w = n * 36 + ks * 8 + tg;
                uint32_t b0 = bp[w], b1 = bp[w + 4];
                mma_f16(acc[0][nt], a[0], b0, b1);
                mma_f16(acc[1][nt], a[1], b0, b1);
            }
        }
        __syncthreads();
    }

    // epilogue: +b2, store float2
    #pragma unroll
    for (int mt = 0; mt < 2; mt++) {
        size_t r0 = r0g + 32 * wm + 16 * mt + g;
        size_t r1 = r0 + 8;
        #pragma unroll
        for (int nt = 0; nt < 8; nt++) {
            int j0 = wn * 64 + nt * 8 + 2 * tg;
            float ba = b2S[j0], bb = b2S[j0 + 1];
            *(float2*)&out[r0 * D_MODEL + j0] = make_float2(acc[mt][nt][0] + ba, acc[mt][nt][1] + bb);
            *(float2*)&out[r1 * D_MODEL + j0] = make_float2(acc[mt][nt][2] + ba, acc[mt][nt][3] + bb);
        }
    }
}

// ---------------- launch ----------------
extern "C" void kernel_launch(void* const* d_in, const int* in_sizes, int n_in,
                              void* d_out, int out_size) {
    const int*   byte_ids = (const int*)  d_in[0];
    const float* fb       = (const float*)d_in[1];
    const float* w1       = (const float*)d_in[2];
    const float* b1       = (const float*)d_in[3];
    const float* gamma    = (const float*)d_in[4];
    const float* beta     = (const float*)d_in[5];
    const float* w2       = (const float*)d_in[6];
    const float* b2v      = (const float*)d_in[7];
    float* out = (float*)d_out;

    (void)in_sizes; (void)n_in; (void)out_size;

    cudaFuncSetAttribute(spectral_kernel, cudaFuncAttributeMaxDynamicSharedMemorySize,
                         SPEC_SMEM_FLOATS * (int)sizeof(float));
    cudaFuncSetAttribute(gemm1_kernel, cudaFuncAttributeMaxDynamicSharedMemorySize, G1_SMEM_BYTES);
    cudaFuncSetAttribute(gemm2_kernel, cudaFuncAttributeMaxDynamicSharedMemorySize, G2_SMEM_BYTES);

    prep_kernel<<<768, 256>>>(w1, w2);
    spectral_kernel<<<B_SZ, 256, SPEC_SMEM_FLOATS * sizeof(float)>>>(byte_ids, fb, w1, b1);
    gemm1_kernel<<<B_SZ * (T_LEN / 64), 512, G1_SMEM_BYTES>>>(gamma, beta);
    gemm2_kernel<<<NROWS / 128, 512, G2_SMEM_BYTES>>>(b2v, out);
}

// round 10
// speedup vs baseline: 3.2618x; 1.7687x over previous
#include <cuda_runtime.h>
#include <cuda_fp16.h>
#include <math.h>
#include <stdint.h>

// Problem constants
#define T_LEN   4096
#define B_SZ    32
#define D_MODEL 256
#define H_DIM   512
#define KFREQ   128
#define LN_EPS  1e-5f
#define PHSTEP  1.5339807878856412e-3f   // 2*pi/4096
#define NROWS   (B_SZ * T_LEN)           // 131072

// ---------------- device scratch (static; no allocations) ----------------
__device__ float g_ren[B_SZ * KFREQ];
__device__ float g_imn[B_SZ * KFREQ];
__device__ float g_base[B_SZ * H_DIM];
__device__ __align__(16) __half g_w1h[4 * 512 * 40];     // w1b fp16, 4 k32-chunks, [n][k] LDk=40
__device__ __align__(16) __half g_w2h[8 * 256 * 72];     // w2  fp16, 8 k64-chunks, [n][k] LDk=72
__device__ __align__(16) __half g_h[(size_t)NROWS * H_DIM]; // 128MB intermediate (post-GELU fp16)

// ---------------- helpers ----------------
__device__ __forceinline__ uint32_t smem_u32(const void* p) {
    uint32_t a;
    asm("{ .reg .u64 t; cvta.to.shared.u64 t, %1; cvt.u32.u64 %0, t; }" : "=r"(a) : "l"(p));
    return a;
}
__device__ __forceinline__ void cp16(uint32_t dst, const void* src) {
    asm volatile("cp.async.cg.shared.global [%0], [%1], 16;" :: "r"(dst), "l"(src) : "memory");
}
__device__ __forceinline__ void cp_commit() { asm volatile("cp.async.commit_group;" ::: "memory"); }
__device__ __forceinline__ void cp_wait1()  { asm volatile("cp.async.wait_group 1;" ::: "memory"); }
__device__ __forceinline__ void cp_wait0()  { asm volatile("cp.async.wait_group 0;" ::: "memory"); }

// ldmatrix x4: loads 4 8x8 b16 matrices; lanes 8i..8i+7 supply row addrs of matrix i.
__device__ __forceinline__ void ldm4(uint32_t& r0, uint32_t& r1, uint32_t& r2, uint32_t& r3,
                                     uint32_t a) {
    asm volatile("ldmatrix.sync.aligned.m8n8.x4.shared.b16 {%0,%1,%2,%3}, [%4];"
                 : "=r"(r0), "=r"(r1), "=r"(r2), "=r"(r3) : "r"(a));
}

// m16n8k16 row.col f32.f16.f16.f32
__device__ __forceinline__ void mma_f16(float* d, const uint32_t* a, uint32_t b0, uint32_t b1) {
    asm volatile(
        "mma.sync.aligned.m16n8k16.row.col.f32.f16.f16.f32 "
        "{%0,%1,%2,%3}, {%4,%5,%6,%7}, {%8,%9}, {%0,%1,%2,%3};"
        : "+f"(d[0]), "+f"(d[1]), "+f"(d[2]), "+f"(d[3])
        : "r"(a[0]), "r"(a[1]), "r"(a[2]), "r"(a[3]), "r"(b0), "r"(b1));
}

// tanh-form GELU with HW tanh (MUFU): ~4 instr vs ~14 for erff
__device__ __forceinline__ float gelu_t(float y) {
    float u = 0.7978845608028654f * __fmaf_rn(0.044715f * y, y * y, y);
    float t;
    asm("tanh.approx.f32 %0, %1;" : "=f"(t) : "f"(u));
    return 0.5f * y * (1.0f + t);
}

// ---------------- kernel: weight prep (fp16 images, padded conflict-free layouts) ----------------
__global__ __launch_bounds__(256) void prep_kernel(const float* __restrict__ w1,
                                                   const float* __restrict__ w2) {
    int i = blockIdx.x * 256 + threadIdx.x;
    if (i < 512 * 128) {                       // w1b: n=0..511, k=0..127
        int n = i >> 7, k = i & 127;
        g_w1h[((k >> 5) * 512 + n) * 40 + (k & 31)] = __float2half_rn(w1[(KFREQ + k) * H_DIM + n]);
    } else {
        int j = i - 512 * 128;                 // w2: n=0..255, k=0..511
        if (j < 256 * 512) {
            int n = j >> 9, k = j & 511;
            g_w2h[((k >> 6) * 256 + n) * 72 + (k & 63)] = __float2half_rn(w2[k * D_MODEL + n]);
        }
    }
}

// ---------------- kernel: spectral (DFT bins, normalized phase, base) ----------------
#define SPEC_SMEM_FLOATS (T_LEN * 3 + KFREQ)
__global__ __launch_bounds__(256) void spectral_kernel(
    const int* __restrict__ byte_ids,
    const float* __restrict__ freq_bands,
    const float* __restrict__ w1,
    const float* __restrict__ b1)
{
    extern __shared__ float sm[];
    float* sig  = sm;
    float* lc   = sm + T_LEN;
    float* ls   = sm + 2 * T_LEN;
    float* magS = sm + 3 * T_LEN;

    int b   = blockIdx.x;
    int tid = threadIdx.x;

    for (int i = tid; i < T_LEN; i += 256) {
        sig[i] = (float)byte_ids[b * T_LEN + i] * (1.0f / 127.5f) - 1.0f;
        float s, c;
        sincosf((float)i * PHSTEP, &s, &c);
        lc[i] = c; ls[i] = s;
    }
    __syncthreads();

    int warp = tid >> 5, lane = tid & 31;
    for (int f = warp; f < KFREQ; f += 8) {
        float cacc = 0.f, sacc = 0.f;
        int idx  = (lane * f) & (T_LEN - 1);
        int step = (32 * f) & (T_LEN - 1);
        for (int i = lane; i < T_LEN; i += 32) {
            float sv = sig[i];
            cacc += sv * lc[idx];
            sacc += sv * ls[idx];
            idx = (idx + step) & (T_LEN - 1);
        }
        #pragma unroll
        for (int o = 16; o; o >>= 1) {
            cacc += __shfl_xor_sync(0xffffffffu, cacc, o);
            sacc += __shfl_xor_sync(0xffffffffu, sacc, o);
        }
        if (lane == 0) {
            float re = cacc, im = -sacc;
            float hyp = sqrtf(re * re + im * im);
            float rn = 1.0f, in_ = 0.0f;
            if (hyp > 1e-30f) { float inv = 1.0f / hyp; rn = re * inv; in_ = im * inv; }
            g_ren[b * KFREQ + f] = rn;
            g_imn[b * KFREQ + f] = in_;
            magS[f] = hyp * freq_bands[f];
        }
    }
    __syncthreads();

    for (int j = tid; j < H_DIM; j += 256) {
        float acc = b1[j];
        for (int f = 0; f < KFREQ; f++)
            acc += magS[f] * w1[f * H_DIM + j];
        g_base[b * H_DIM + j] = acc;
    }
}

// ---------------- kernel: GEMM1 + LN + GELU -> g_h (fp16) ----------------
// C(64x512) = A(64x128) @ W1b(128x512); grid = 2048 (32 b x 64 tiles), 512 threads (16 warps: 2m x 8n)
// Warp tile 32m x 64n. A smem [64][136] halfwords (272 B/row). B chunks [512][40] hw (80 B/row), dbl-buffered.
#define G1_OFF_A    0
#define G1_OFF_B    17408
#define G1_OFF_LN1  99328
#define G1_OFF_LN2  101376
#define G1_OFF_BASE 103424
#define G1_OFF_GAM  105472
#define G1_OFF_BET  107520
#define G1_OFF_IMN  109568
#define G1_OFF_REN  110080
#define G1_SMEM_BYTES 110592

__global__ __launch_bounds__(512, 1) void gemm1_kernel(
    const float* __restrict__ gamma,
    const float* __restrict__ beta)
{
    extern __shared__ char smc[];
    __half* As   = (__half*)(smc + G1_OFF_A);
    float*  ln1  = (float*)(smc + G1_OFF_LN1);
    float*  ln2  = (float*)(smc + G1_OFF_LN2);
    float*  baseS= (float*)(smc + G1_OFF_BASE);
    float*  gamS = (float*)(smc + G1_OFF_GAM);
    float*  betS = (float*)(smc + G1_OFF_BET);
    float*  imnS = (float*)(smc + G1_OFF_IMN);
    float*  renS = (float*)(smc + G1_OFF_REN);

    int tid  = threadIdx.x;
    int warp = tid >> 5, lane = tid & 31;
    int g    = lane >> 2, tg = lane & 3;
    int wm   = warp >> 3, wn = warp & 7;      // 2 x 8
    int b    = blockIdx.x >> 6;
    int t0   = (blockIdx.x & 63) * 64;

    // ldmatrix per-lane row selectors
    int mrow  = (lane & 7) | (lane & 8);      // 0..15
    int koffA = (lane & 16) ? 16 : 0;         // +8 hw
    int nrow  = lane & 7;
    int nadd  = (lane & 16) ? 8 : 0;          // matrices 2,3 -> +8 n
    int koffB = (lane & 8) ? 16 : 0;          // matrices 1,3 -> +8 k

    if (tid < 128) { imnS[tid] = g_imn[b * KFREQ + tid]; renS[tid] = g_ren[b * KFREQ + tid]; }
    baseS[tid] = g_base[b * H_DIM + tid];
    gamS[tid]  = gamma[tid];
    betS[tid]  = beta[tid];

    uint32_t bbuf[2] = { smem_u32(smc + G1_OFF_B), smem_u32(smc + G1_OFF_B + 40960) };
    // issue B chunk 0 immediately (overlaps with A generation below)
    {
        const char* src = (const char*)g_w1h;
        #pragma unroll
        for (int i = 0; i < 5; i++) { int e = tid + i * 512; cp16(bbuf[0] + e * 16, src + e * 16); }
        cp_commit();
    }
    __syncthreads();   // imnS/renS ready for A-gen

    // generate A (64 x 128) fp16 into smem, LDk=136 halfwords
    for (int e = tid; e < 64 * 128; e += 512) {
        int m = e >> 7, k = e & 127;
        int idx = ((t0 + m) * k) & (T_LEN - 1);
        if (idx >= T_LEN / 2) idx -= T_LEN;
        float s, c;
        __sincosf((float)idx * PHSTEP, &s, &c);
        As[m * 136 + k] = __float2half_rn(imnS[k] * c + renS[k] * s);
    }

    float acc[2][8][4];
    #pragma unroll
    for (int mt = 0; mt < 2; mt++)
        #pragma unroll
        for (int nt = 0; nt < 8; nt++)
            #pragma unroll
            for (int d = 0; d < 4; d++) acc[mt][nt][d] = 0.f;

    uint32_t aAdr = smem_u32(As) + (32 * wm + mrow) * 272 + koffA;
    uint32_t bOff = (uint32_t)(wn * 64 + nrow + nadd) * 80 + koffB;

    for (int c = 0; c < 4; c++) {
        if (c < 3) {
            const char* src = (const char*)g_w1h + (c + 1) * 40960;
            uint32_t dst = bbuf[(c + 1) & 1];
            #pragma unroll
            for (int i = 0; i < 5; i++) { int e = tid + i * 512; cp16(dst + e * 16, src + e * 16); }
            cp_commit();
            cp_wait1();
        } else {
            cp_wait0();
        }
        __syncthreads();

        uint32_t bbase = bbuf[c & 1] + bOff;
        uint32_t abase = aAdr + c * 64;     // c*32 hw
        #pragma unroll
        for (int ks = 0; ks < 2; ks++) {
            uint32_t A0[4], A1[4];
            ldm4(A0[0], A0[1], A0[2], A0[3], abase + ks * 32);
            ldm4(A1[0], A1[1], A1[2], A1[3], abase + 16 * 272 + ks * 32);
            #pragma unroll
            for (int ntp = 0; ntp < 4; ntp++) {
                uint32_t b0, b1, b2, b3;
                ldm4(b0, b1, b2, b3, bbase + ntp * (16 * 80) + ks * 32);
                mma_f16(acc[0][2 * ntp],     A0, b0, b1);
                mma_f16(acc[1][2 * ntp],     A1, b0, b1);
                mma_f16(acc[0][2 * ntp + 1], A0, b2, b3);
                mma_f16(acc[1][2 * ntp + 1], A1, b2, b3);
            }
        }
        __syncthreads();
    }

    // ---- +base, LN stats ----
    #pragma unroll
    for (int mt = 0; mt < 2; mt++)
        #pragma unroll
        for (int nt = 0; nt < 8; nt++) {
            int j0 = wn * 64 + nt * 8 + 2 * tg;
            acc[mt][nt][0] += baseS[j0];
            acc[mt][nt][1] += baseS[j0 + 1];
            acc[mt][nt][2] += baseS[j0];
            acc[mt][nt][3] += baseS[j0 + 1];
        }

    #pragma unroll
    for (int mt = 0; mt < 2; mt++)
        #pragma unroll
        for (int h = 0; h < 2; h++) {
            float s1 = 0.f, s2 = 0.f;
            #pragma unroll
            for (int nt = 0; nt < 8; nt++) {
                float v0 = acc[mt][nt][2 * h], v1 = acc[mt][nt][2 * h + 1];
                s1 += v0 + v1; s2 += v0 * v0 + v1 * v1;
            }
            s1 += __shfl_xor_sync(0xffffffffu, s1, 1); s2 += __shfl_xor_sync(0xffffffffu, s2, 1);
            s1 += __shfl_xor_sync(0xffffffffu, s1, 2); s2 += __shfl_xor_sync(0xffffffffu, s2, 2);
            if (tg == 0) {
                int r = 32 * wm + 16 * mt + g + 8 * h;
                ln1[r * 8 + wn] = s1;
                ln2[r * 8 + wn] = s2;
            }
        }
    __syncthreads();

    float mean[2][2], rstd[2][2];
    #pragma unroll
    for (int mt = 0; mt < 2; mt++)
        #pragma unroll
        for (int h = 0; h < 2; h++) {
            int r = 32 * wm + 16 * mt + g + 8 * h;
            float t1 = 0.f, t2 = 0.f;
            #pragma unroll
            for (int w = 0; w < 8; w++) { t1 += ln1[r * 8 + w]; t2 += ln2[r * 8 + w]; }
            float mu = t1 * (1.0f / H_DIM);
            float va = t2 * (1.0f / H_DIM) - mu * mu;
            mean[mt][h] = mu;
            rstd[mt][h] = rsqrtf(va + LN_EPS);
        }

    // ---- GELU (tanh form) + store fp16 to g_h ----
    #pragma unroll
    for (int mt = 0; mt < 2; mt++) {
        size_t rg0 = (size_t)(b * T_LEN + t0 + 32 * wm + 16 * mt + g);
        size_t rg1 = rg0 + 8;
        #pragma unroll
        for (int nt = 0; nt < 8; nt++) {
            int j0 = wn * 64 + nt * 8 + 2 * tg;
            float ga = gamS[j0], gb = gamS[j0 + 1], ba = betS[j0], bb = betS[j0 + 1];
            float y00 = (acc[mt][nt][0] - mean[mt][0]) * rstd[mt][0] * ga + ba;
            float y01 = (acc[mt][nt][1] - mean[mt][0]) * rstd[mt][0] * gb + bb;
            float y10 = (acc[mt][nt][2] - mean[mt][1]) * rstd[mt][1] * ga + ba;
            float y11 = (acc[mt][nt][3] - mean[mt][1]) * rstd[mt][1] * gb + bb;
            *(__half2*)&g_h[rg0 * H_DIM + j0] = __floats2half2_rn(gelu_t(y00), gelu_t(y01));
            *(__half2*)&g_h[rg1 * H_DIM + j0] = __floats2half2_rn(gelu_t(y10), gelu_t(y11));
        }
    }
}

// ---------------- kernel: GEMM2 + bias -> out ----------------
// C(128x256) = h(128x512) @ W2(512x256); grid = 1024, 512 threads (16 warps: 4m x 4n)
// Warp tile 32m x 64n. k64 chunks: A [128][72]hw (144 B/row), B [256][72]hw, both double-buffered.
#define G2_OFF_A   0
#define G2_OFF_B   36864
#define G2_OFF_B2  110592
#define G2_SMEM_BYTES 111616

__global__ __launch_bounds__(512, 1) void gemm2_kernel(
    const float* __restrict__ b2v,
    float* __restrict__ out)
{
    extern __shared__ char smc[];
    float* b2S = (float*)(smc + G2_OFF_B2);

    int tid  = threadIdx.x;
    int warp = tid >> 5, lane = tid & 31;
    int g    = lane >> 2, tg = lane & 3;
    int wm   = warp & 3, wn = warp >> 2;      // 4 x 4
    size_t r0g = (size_t)blockIdx.x * 128;

    int mrow  = (lane & 7) | (lane & 8);
    int koffA = (lane & 16) ? 16 : 0;
    int nrow  = lane & 7;
    int nadd  = (lane & 16) ? 8 : 0;
    int koffB = (lane & 8) ? 16 : 0;

    if (tid < 256) b2S[tid] = b2v[tid];

    uint32_t abuf[2] = { smem_u32(smc + G2_OFF_A), smem_u32(smc + G2_OFF_A + 18432) };
    uint32_t bbuf[2] = { smem_u32(smc + G2_OFF_B), smem_u32(smc + G2_OFF_B + 36864) };

    // prefetch chunk 0
    {
        const char* hb = (const char*)g_h;
        #pragma unroll
        for (int i = 0; i < 2; i++) {
            int e = tid + i * 512;            // 1024 x 16B for A
            int m = e >> 3, q = e & 7;
            cp16(abuf[0] + m * 144 + q * 16, hb + ((r0g + m) * 1024) + q * 16);
        }
        const char* wb = (const char*)g_w2h;
        for (int e = tid; e < 2304; e += 512) cp16(bbuf[0] + e * 16, wb + e * 16);
        cp_commit();
    }

    float acc[2][8][4];
    #pragma unroll
    for (int mt = 0; mt < 2; mt++)
        #pragma unroll
        for (int nt = 0; nt < 8; nt++)
            #pragma unroll
            for (int d = 0; d < 4; d++) acc[mt][nt][d] = 0.f;

    uint32_t aOff = (uint32_t)(32 * wm + mrow) * 144 + koffA;
    uint32_t bOff = (uint32_t)(wn * 64 + nrow + nadd) * 144 + koffB;

    for (int c = 0; c < 8; c++) {
        if (c < 7) {
            int nb = (c + 1) & 1;
            const char* hb = (const char*)g_h;
            #pragma unroll
            for (int i = 0; i < 2; i++) {
                int e = tid + i * 512;
                int m = e >> 3, q = e & 7;
                cp16(abuf[nb] + m * 144 + q * 16, hb + ((r0g + m) * 1024) + (size_t)(c + 1) * 128 + q * 16);
            }
            const char* wb = (const char*)g_w2h + (size_t)(c + 1) * 36864;
            for (int e = tid; e < 2304; e += 512) cp16(bbuf[nb] + e * 16, wb + e * 16);
            cp_commit();
            cp_wait1();
        } else {
            cp_wait0();
        }
        __syncthreads();

        uint32_t abase = abuf[c & 1] + aOff;
        uint32_t bbase = bbuf[c & 1] + bOff;
        #pragma unroll
        for (int ks = 0; ks < 4; ks++) {
            uint32_t A0[4], A1[4];
            ldm4(A0[0], A0[1], A0[2], A0[3], abase + ks * 32);
            ldm4(A1[0], A1[1], A1[2], A1[3], abase + 16 * 144 + ks * 32);
            #pragma unroll
            for (int ntp = 0; ntp < 4; ntp++) {
                uint32_t b0, b1, b2, b3;
                ldm4(b0, b1, b2, b3, bbase + ntp * (16 * 144) + ks * 32);
                mma_f16(acc[0][2 * ntp],     A0, b0, b1);
                mma_f16(acc[1][2 * ntp],     A1, b0, b1);
                mma_f16(acc[0][2 * ntp + 1], A0, b2, b3);
                mma_f16(acc[1][2 * ntp + 1], A1, b2, b3);
            }
        }
        __syncthreads();
    }

    // epilogue: +b2, store float2
    #pragma unroll
    for (int mt = 0; mt < 2; mt++) {
        size_t r0 = r0g + 32 * wm + 16 * mt + g;
        size_t r1 = r0 + 8;
        #pragma unroll
        for (int nt = 0; nt < 8; nt++) {
            int j0 = wn * 64 + nt * 8 + 2 * tg;
            float ba = b2S[j0], bb = b2S[j0 + 1];
            *(float2*)&out[r0 * D_MODEL + j0] = make_float2(acc[mt][nt][0] + ba, acc[mt][nt][1] + bb);
            *(float2*)&out[r1 * D_MODEL + j0] = make_float2(acc[mt][nt][2] + ba, acc[mt][nt][3] + bb);
        }
    }
}

// ---------------- launch ----------------
extern "C" void kernel_launch(void* const* d_in, const int* in_sizes, int n_in,
                              void* d_out, int out_size) {
    const int*   byte_ids = (const int*)  d_in[0];
    const float* fb       = (const float*)d_in[1];
    const float* w1       = (const float*)d_in[2];
    const float* b1       = (const float*)d_in[3];
    const float* gamma    = (const float*)d_in[4];
    const float* beta     = (const float*)d_in[5];
    const float* w2       = (const float*)d_in[6];
    const float* b2v      = (const float*)d_in[7];
    float* out = (float*)d_out;

    (void)in_sizes; (void)n_in; (void)out_size;

    cudaFuncSetAttribute(spectral_kernel, cudaFuncAttributeMaxDynamicSharedMemorySize,
                         SPEC_SMEM_FLOATS * (int)sizeof(float));
    cudaFuncSetAttribute(gemm1_kernel, cudaFuncAttributeMaxDynamicSharedMemorySize, G1_SMEM_BYTES);
    cudaFuncSetAttribute(gemm2_kernel, cudaFuncAttributeMaxDynamicSharedMemorySize, G2_SMEM_BYTES);

    prep_kernel<<<768, 256>>>(w1, w2);
    spectral_kernel<<<B_SZ, 256, SPEC_SMEM_FLOATS * sizeof(float)>>>(byte_ids, fb, w1, b1);
    gemm1_kernel<<<B_SZ * (T_LEN / 64), 512, G1_SMEM_BYTES>>>(gamma, beta);
    gemm2_kernel<<<NROWS / 128, 512, G2_SMEM_BYTES>>>(b2v, out);
}